// round 6
// baseline (speedup 1.0000x reference)
#include <cuda_runtime.h>
#include <cuda_bf16.h>
#include <cstdint>

// ---------------- problem constants ----------------
#define NS      512
#define KSEG    16
#define SEGD    8192
#define FSTRIDE (KSEG * SEGD)
#define OP_SCALE 1.1952286093343936f   // 1/sqrt(0.7) folded per operand

// ---------------- fused kernel config ----------------
#define NSM     152                    // 1 CTA per SM
#define NTHREADS 640                   // 16 MMA warps + 4 convert warps
#define MT      128
#define CK      64                     // bf16 per chunk (128B rows, SW128)
#define KQ      2048                   // K per unit (quarter)
#define CHPU    (KQ / CK)              // 32 chunks per unit
#define STAGES  4
#define OP_BYTES    (MT * 128)         // 16384
#define STAGE_BYTES (2 * OP_BYTES)     // 32768
#define SMEM_DYN (1024 + STAGES * STAGE_BYTES)  // 132096

#define NTILES  4
#define NPAIRS  10
#define UPSEG   (NPAIRS * 4)           // 40 units per segment
#define UNITS   (UPSEG * KSEG)         // 640

// ---------------- device scratch ----------------
__device__ __align__(16) __nv_bfloat16 g_fb16[(size_t)KSEG * NS * SEGD]; // [k][n][d]
__device__ float g_simsP[(size_t)4 * KSEG * NS * NS];  // [kq][seg][a][b]
__device__ float g_partials[1024];
__device__ int   g_red_count;
__device__ int   g_unit;               // work-queue head (self-resetting)
__device__ int   g_segcnt[KSEG];
__device__ int   g_segflag[KSEG];

// ---------------- helpers ----------------
__device__ __forceinline__ uint32_t smem_u32(const void* p) {
    uint32_t a;
    asm("{ .reg .u64 t; cvta.to.shared.u64 t, %1; cvt.u32.u64 %0, t; }" : "=r"(a) : "l"(p));
    return a;
}
#define CP16(dst, src) \
    asm volatile("cp.async.cg.shared.global [%0], [%1], 16;" :: "r"(dst), "l"(src))
#define CP_COMMIT() asm volatile("cp.async.commit_group;" ::: "memory")
template <int N> __device__ __forceinline__ void cp_wait() {
    asm volatile("cp.async.wait_group %0;" :: "n"(N) : "memory");
}
#define SW128(o) ((o) ^ (((o) >> 3) & 0x70))
#define BAR_MMA()  asm volatile("bar.sync 1, 512;" ::: "memory")
#define BAR_CONV() asm volatile("bar.sync 2, 128;" ::: "memory")

__device__ __forceinline__ void ldsm_x4(uint32_t& r0, uint32_t& r1, uint32_t& r2, uint32_t& r3,
                                        uint32_t addr) {
    asm volatile("ldmatrix.sync.aligned.m8n8.x4.shared.b16 {%0,%1,%2,%3}, [%4];"
                 : "=r"(r0), "=r"(r1), "=r"(r2), "=r"(r3) : "r"(addr));
}
__device__ __forceinline__ void mma16816(float* c, const uint32_t* a, uint32_t b0, uint32_t b1) {
    asm volatile(
        "mma.sync.aligned.m16n8k16.row.col.f32.bf16.bf16.f32 "
        "{%0,%1,%2,%3}, {%4,%5,%6,%7}, {%8,%9}, {%0,%1,%2,%3};"
        : "+f"(c[0]), "+f"(c[1]), "+f"(c[2]), "+f"(c[3])
        : "r"(a[0]), "r"(a[1]), "r"(a[2]), "r"(a[3]), "r"(b0), "r"(b1));
}

// ---------------------------------------------------------------------------
// Fused convert + GEMM. 152 CTAs (1/SM), 640 threads.
//   warps 0-15 : HMMA GEMM (512 threads, named barrier 1), 4x4 layout,
//                32x32 warp tiles over 128x128 CTA tile, 4-stage cp.async.
//   warps 16-19: f32->bf16 producer, seg-by-seg, per-seg release flags.
// Units = (tile-pair, K-quarter), seg-major order, pulled from an atomic
// queue (output-deterministic: each unit writes a disjoint partial buffer).
// ---------------------------------------------------------------------------
__global__ void __launch_bounds__(NTHREADS)
fused_kernel(const float* __restrict__ F) {
    extern __shared__ __align__(1024) char smem_raw[];
    __shared__ int s_unit;
    const int tid = threadIdx.x;
    const int cta = blockIdx.x;

    if (tid >= 512) {
        // ---------------- producer: convert warps ----------------
        const int tc = tid - 512;                   // 0..127
        const uint32_t UPS = (NS * SEGD) / 8;       // 524288 8-elem groups / seg
        const uint32_t lo = (uint32_t)(((uint64_t)cta * UPS) / NSM);
        const uint32_t hi = (uint32_t)(((uint64_t)(cta + 1) * UPS) / NSM);
        for (int s = 0; s < KSEG; s++) {
#pragma unroll 4
            for (uint32_t i = lo + tc; i < hi; i += 128) {
                uint32_t e = i * 8;
                uint32_t n = e >> 13, d = e & 8191;
                const float4* src = (const float4*)(F + (size_t)n * FSTRIDE + s * SEGD + d);
                float4 a = src[0], b = src[1];
                a.x *= OP_SCALE; a.y *= OP_SCALE; a.z *= OP_SCALE; a.w *= OP_SCALE;
                b.x *= OP_SCALE; b.y *= OP_SCALE; b.z *= OP_SCALE; b.w *= OP_SCALE;
                __nv_bfloat162 h0 = __floats2bfloat162_rn(a.x, a.y);
                __nv_bfloat162 h1 = __floats2bfloat162_rn(a.z, a.w);
                __nv_bfloat162 h2 = __floats2bfloat162_rn(b.x, b.y);
                __nv_bfloat162 h3 = __floats2bfloat162_rn(b.z, b.w);
                uint4 v;
                v.x = *(uint32_t*)&h0; v.y = *(uint32_t*)&h1;
                v.z = *(uint32_t*)&h2; v.w = *(uint32_t*)&h3;
                *(uint4*)(g_fb16 + ((size_t)s * NS + n) * SEGD + d) = v;
            }
            BAR_CONV();
            if (tc == 0) {
                __threadfence();
                if (atomicAdd(&g_segcnt[s], 1) == NSM - 1) {
                    __threadfence();
                    atomicExch(&g_segflag[s], 1);   // release segment s
                }
            }
        }
        return;
    }

    // ---------------- consumer: 16 MMA warps ----------------
    uint32_t sbase = (smem_u32(smem_raw) + 1023) & ~1023u;
    const int lane = tid & 31;
    const int wid  = tid >> 5;
    const int wm   = wid & 3;            // 4 warps along M
    const int wn   = wid >> 2;           // 4 warps along N
    const int lrow = lane & 15;
    const int khf  = (lane >> 4) & 1;
    const int gid  = lane >> 2, tig = lane & 3;

    int lastSeg = -1;

    for (;;) {
        if (tid == 0) s_unit = atomicAdd(&g_unit, 1);
        BAR_MMA();
        const int u = s_unit;
        if (u >= UNITS) break;

        const int seg = u / UPSEG;
        const int r   = u - seg * UPSEG;
        const int kq  = r & 3;
        int p = r >> 2;
        int bi = 0;
        while (p >= NTILES - bi) { p -= NTILES - bi; bi++; }
        const int bj = bi + p;

        if (seg != lastSeg) {                        // acquire producer flag
            if (tid == 0) {
                while (atomicAdd(&g_segflag[seg], 0) == 0) __nanosleep(200);
            }
            BAR_MMA();
            lastSeg = seg;
        }

        const __nv_bfloat16* gA = g_fb16 + ((size_t)seg * NS + bi * MT) * SEGD + kq * KQ;
        const __nv_bfloat16* gB = g_fb16 + ((size_t)seg * NS + bj * MT) * SEGD + kq * KQ;

        float acc[2][4][4];
#pragma unroll
        for (int i = 0; i < 2; i++)
#pragma unroll
            for (int j = 0; j < 4; j++)
#pragma unroll
                for (int q = 0; q < 4; q++) acc[i][j][q] = 0.0f;

        auto load_chunk = [&](int c) {
            uint32_t st = sbase + (c & (STAGES - 1)) * STAGE_BYTES;
            int kb = c * CK;
#pragma unroll
            for (int i = 0; i < 4; i++) {            // 2048 float4s over 512 thr
                int q = i * 512 + tid;
                int row = q >> 3, g = q & 7;
                if (row < MT) {
                    CP16(st + SW128(row * 128 + g * 16),
                         gA + (size_t)row * SEGD + kb + g * 8);
                } else {
                    int r2 = row - MT;
                    CP16(st + OP_BYTES + SW128(r2 * 128 + g * 16),
                         gB + (size_t)r2 * SEGD + kb + g * 8);
                }
            }
            CP_COMMIT();
        };

        auto compute = [&](int cs) {
            uint32_t sa = sbase + cs * STAGE_BYTES;
            uint32_t sb = sa + OP_BYTES;
#pragma unroll
            for (int ks = 0; ks < 4; ks++) {
                const int kb = ks * 32 + khf * 16;
                uint32_t a[2][4], bf[2][4];
#pragma unroll
                for (int im = 0; im < 2; im++) {
                    int row = wm * 32 + im * 16 + lrow;
                    ldsm_x4(a[im][0], a[im][1], a[im][2], a[im][3],
                            sa + SW128(row * 128 + kb));
                }
#pragma unroll
                for (int j2 = 0; j2 < 2; j2++) {
                    int row = wn * 32 + j2 * 16 + lrow;
                    ldsm_x4(bf[j2][0], bf[j2][1], bf[j2][2], bf[j2][3],
                            sb + SW128(row * 128 + kb));
                }
#pragma unroll
                for (int im = 0; im < 2; im++)
#pragma unroll
                    for (int jn = 0; jn < 4; jn++)
                        mma16816(acc[im][jn], a[im],
                                 bf[jn >> 1][jn & 1], bf[jn >> 1][2 + (jn & 1)]);
            }
        };

        load_chunk(0); load_chunk(1); load_chunk(2);
        for (int c = 0; c < CHPU; c++) {
            cp_wait<2>();
            BAR_MMA();
            compute(c & (STAGES - 1));
            if (c + 3 < CHPU) load_chunk(c + 3);
            else CP_COMMIT();
        }

        float* Cb = g_simsP + (((size_t)kq * KSEG + seg) << 18);
#pragma unroll
        for (int im = 0; im < 2; im++) {
#pragma unroll
            for (int jn = 0; jn < 4; jn++) {
                int r0 = bi * MT + wm * 32 + im * 16 + gid;
                int c0 = bj * MT + wn * 32 + jn * 8 + tig * 2;
                *(float2*)&Cb[(size_t)r0 * NS + c0] =
                    make_float2(acc[im][jn][0], acc[im][jn][1]);
                *(float2*)&Cb[(size_t)(r0 + 8) * NS + c0] =
                    make_float2(acc[im][jn][2], acc[im][jn][3]);
            }
        }
        // note: no barrier needed before next unit's load_chunk(0): stage 0 was
        // consumed (cp_wait<0>-equivalent reached via c=CHPU-1 path) -- the
        // final cp_wait<2>/BAR pair of this unit ordered all warps past stage 0.
    }
}

// ---------------------------------------------------------------------------
// Loss over upper tile-pairs only (off-diagonal weight 2). Sums 4 K-partials,
// top-4-of-16 exp ratio, masked; deterministic tree reduce; last block writes
// the mean and resets queue/flags/counters for graph replay.
// ---------------------------------------------------------------------------
__global__ __launch_bounds__(256) void reduce_kernel(const int* __restrict__ lab,
                                                     float* __restrict__ out) {
    const int t = threadIdx.x;
    // dtype detect: odd words 1..511 all zero <=> int64 (labels 0..9)
    int viol = (lab[2 * t + 1] != 0) ? 1 : 0;
    int is_int32 = __syncthreads_or(viol);

    const int tp    = blockIdx.x >> 6;            // tile pair 0..9
    const int local = ((blockIdx.x & 63) << 8) + t;
    int pp = tp;
    int bi = 0;
    while (pp >= NTILES - bi) { pp -= NTILES - bi; bi++; }
    const int bj = bi + pp;

    const int a = bi * MT + (local >> 7);
    const int b = bj * MT + (local & 127);
    const size_t idx = (size_t)a * NS + b;

    float v[KSEG];
    float m = -1e30f;
#pragma unroll
    for (int k = 0; k < KSEG; k++) {
        float s = 0.0f;
#pragma unroll
        for (int q = 0; q < 4; q++)
            s += g_simsP[(((size_t)q * KSEG + k) << 18) + idx];
        v[k] = s;
        m = fmaxf(m, s);
    }
    float tot = 0.0f, t0 = 0.0f, t1 = 0.0f, t2 = 0.0f, t3 = 0.0f;
#pragma unroll
    for (int k = 0; k < KSEG; k++) {
        const float e = __expf(v[k] - m);
        tot += e;
        if (e > t0)      { t3 = t2; t2 = t1; t1 = t0; t0 = e; }
        else if (e > t1) { t3 = t2; t2 = t1; t1 = e; }
        else if (e > t2) { t3 = t2; t2 = e; }
        else if (e > t3) { t3 = e; }
    }
    const int la = is_int32 ? lab[a] : lab[2 * a];
    const int lb = is_int32 ? lab[b] : lab[2 * b];
    float loss = 0.0f;
    if (a != b && la == lb) {
        const float w = (bi == bj) ? 1.0f : 2.0f;
        loss = -w * __logf((t0 + t1 + t2 + t3) / tot);
    }

    __shared__ float red[256];
    red[t] = loss;
    __syncthreads();
#pragma unroll
    for (int s = 128; s > 0; s >>= 1) {
        if (t < s) red[t] += red[t + s];
        __syncthreads();
    }

    __shared__ int isLast;
    if (t == 0) {
        g_partials[blockIdx.x] = red[0];
        __threadfence();
        int c = atomicAdd(&g_red_count, 1);
        isLast = (c == gridDim.x - 1);
    }
    __syncthreads();

    if (isLast) {
        float s = __ldcg(&g_partials[t]) + __ldcg(&g_partials[t + 256]);
        if (t + 512 < 640) s += __ldcg(&g_partials[t + 512]);
        red[t] = s;
        __syncthreads();
#pragma unroll
        for (int sh = 128; sh > 0; sh >>= 1) {
            if (t < sh) red[t] += red[t + sh];
            __syncthreads();
        }
        if (t == 0) {
            out[0] = red[0] / (float)(NS * NS);
            g_red_count = 0;                       // resets for graph replay
            g_unit = 0;
#pragma unroll
            for (int k = 0; k < KSEG; k++) { g_segcnt[k] = 0; g_segflag[k] = 0; }
        }
    }
}

// ---------------------------------------------------------------------------
extern "C" void kernel_launch(void* const* d_in, const int* in_sizes, int n_in,
                              void* d_out, int out_size) {
    const float* features = (const float*)d_in[0];
    const int*   labels   = (const int*)d_in[1];
    (void)in_sizes; (void)n_in; (void)out_size;

    cudaFuncSetAttribute(fused_kernel, cudaFuncAttributeMaxDynamicSharedMemorySize, SMEM_DYN);

    fused_kernel<<<NSM, NTHREADS, SMEM_DYN>>>(features);
    reduce_kernel<<<NPAIRS * 64, 256>>>(labels, (float*)d_out);
}